// round 2
// baseline (speedup 1.0000x reference)
#include <cuda_runtime.h>
#include <math.h>
#include <stdint.h>

// Problem constants
#define Bz 64
#define Tz 512
#define Cz 512
#define Hz 512
#define Gz 2048   // 4*H
#define Mz (Bz*Tz) // 32768

// ---------------- device scratch (static, no allocation) ----------------
__device__ float g_xp[(size_t)Mz * Gz];      // [m][g], m = b*T+t   (256 MB)
__device__ float g_hseq[(size_t)Mz * Hz];    // [m][c]              (64 MB)
__device__ float g_h0[Hz * Bz];              // h buffer [k][b]
__device__ float g_h1[Hz * Bz];
__device__ float g_wt1[Cz * Gz];             // W_ih1 transposed [c][g]
__device__ float g_wt2[Hz * Gz];             // W_ih2 transposed [c][g]
__device__ float g_bias1[Gz];
__device__ float g_bias2[Gz];
__device__ unsigned long long g_bar;         // grid barrier counter (monotonic)

// ---------------- prep: transpose W_ih, fold biases ----------------
__global__ void lstm_prep(const float* __restrict__ Wih1,
                          const float* __restrict__ bih1,
                          const float* __restrict__ bhh1,
                          const float* __restrict__ Wih2,
                          const float* __restrict__ bih2,
                          const float* __restrict__ bhh2)
{
    int i = blockIdx.x * blockDim.x + threadIdx.x;
    if (i < Cz * Gz) {
        int g = i / Cz;
        int c = i - g * Cz;
        g_wt1[(size_t)c * Gz + g] = Wih1[(size_t)g * Cz + c];
        g_wt2[(size_t)c * Gz + g] = Wih2[(size_t)g * Cz + c];
    }
    if (i < Gz) {
        g_bias1[i] = bih1[i] + bhh1[i];
        g_bias2[i] = bih2[i] + bhh2[i];
    }
}

// ---------------- xp GEMM: C[m][g] = sum_c A[m][c]*Wt[c][g] + bias[g] ---
// XLAYOUT=true : A[m][c] = x[b*C*T + c*T + t], m = b*512 + t  (layer 1)
// XLAYOUT=false: A[m][c] = A[m*512 + c]                       (layer 2)
template<bool XLAYOUT>
__global__ void __launch_bounds__(256)
gemm_xp(const float* __restrict__ A,
        const float* __restrict__ Wt,
        const float* __restrict__ bias,
        float* __restrict__ Cout)
{
    __shared__ float As[16][128];
    __shared__ float Bs[16][128];

    const int m0 = blockIdx.y * 128;
    const int g0 = blockIdx.x * 128;
    const int tid = threadIdx.x;
    const int tx = tid & 15;        // 0..15 -> 8 output cols
    const int ty = tid >> 4;        // 0..15 -> 8 output rows

    float acc[8][8];
#pragma unroll
    for (int i = 0; i < 8; i++)
#pragma unroll
        for (int j = 0; j < 8; j++) acc[i][j] = 0.f;

    for (int k0 = 0; k0 < Cz; k0 += 16) {
        // ---- load A tile into As[k][m] ----
        if (XLAYOUT) {
            int c  = tid >> 5;             // 0..7
            int mi = (tid & 31) * 4;       // 0..124
#pragma unroll
            for (int p = 0; p < 2; p++, c += 8) {
                int m = m0 + mi;
                int b = m >> 9;
                int t = m & 511;
                float4 v = *(const float4*)&A[(size_t)b * (Cz * Tz) + (size_t)(k0 + c) * Tz + t];
                *(float4*)&As[c][mi] = v;
            }
        } else {
            int c4 = (tid & 3) * 4;        // 0,4,8,12
            int mi = tid >> 2;             // 0..63
#pragma unroll
            for (int p = 0; p < 2; p++, mi += 64) {
                float4 v = *(const float4*)&A[(size_t)(m0 + mi) * Cz + k0 + c4];
                As[c4 + 0][mi] = v.x;
                As[c4 + 1][mi] = v.y;
                As[c4 + 2][mi] = v.z;
                As[c4 + 3][mi] = v.w;
            }
        }
        // ---- load B tile: Bs[c][g] = Wt[(k0+c)*G + g0+g] ----
        {
            int c  = tid >> 5;             // 0..7
            int g4 = (tid & 31) * 4;       // 0..124
#pragma unroll
            for (int p = 0; p < 2; p++, c += 8) {
                *(float4*)&Bs[c][g4] = *(const float4*)&Wt[(size_t)(k0 + c) * Gz + g0 + g4];
            }
        }
        __syncthreads();

#pragma unroll
        for (int k = 0; k < 16; k++) {
            float a[8], b[8];
            *(float4*)&a[0] = *(float4*)&As[k][ty * 8];
            *(float4*)&a[4] = *(float4*)&As[k][ty * 8 + 4];
            *(float4*)&b[0] = *(float4*)&Bs[k][tx * 8];
            *(float4*)&b[4] = *(float4*)&Bs[k][tx * 8 + 4];
#pragma unroll
            for (int i = 0; i < 8; i++)
#pragma unroll
                for (int j = 0; j < 8; j++)
                    acc[i][j] += a[i] * b[j];
        }
        __syncthreads();
    }

    // ---- epilogue: add bias, store ----
    float bv[8];
#pragma unroll
    for (int j = 0; j < 8; j++) bv[j] = bias[g0 + tx * 8 + j];

#pragma unroll
    for (int i = 0; i < 8; i++) {
        size_t m = (size_t)(m0 + ty * 8 + i);
#pragma unroll
        for (int j = 0; j < 8; j += 4) {
            float4 v;
            v.x = acc[i][j + 0] + bv[j + 0];
            v.y = acc[i][j + 1] + bv[j + 1];
            v.z = acc[i][j + 2] + bv[j + 2];
            v.w = acc[i][j + 3] + bv[j + 3];
            *(float4*)&Cout[m * Gz + g0 + tx * 8 + j] = v;
        }
    }
}

// ---------------- software grid barrier (monotonic counter) ----------------
#define NBLK 128
__device__ __forceinline__ void gridbar()
{
    __syncthreads();
    if (threadIdx.x == 0) {
        unsigned long long a = atomicAdd(&g_bar, 1ULL) + 1ULL;
        unsigned long long target = ((a - 1ULL) / NBLK + 1ULL) * (unsigned long long)NBLK;
        while (*(volatile unsigned long long*)&g_bar < target) { }
        __threadfence();
    }
    __syncthreads();
}

__device__ __forceinline__ float sigmoidf_(float x) { return 1.f / (1.f + expf(-x)); }

// ---------------- persistent recurrent kernel ----------------
// 128 blocks x 128 threads. Block b owns h-cols j0..j0+3 => 16 gate-cols.
// gates[b][gc] = xp[(b*T+t)*G + gc] + sum_k h[k][b] * Whh[gc][k]
__global__ void __launch_bounds__(128)
lstm_rec(const float* __restrict__ Whh,
         const float* __restrict__ xp,
         float* __restrict__ outp,
         int layer)
{
    __shared__ float w_s[Hz][16];   // 32 KB : w_s[k][lc] = Whh[gc(lc)][k]
    __shared__ float h_s[32][64];   //  8 KB : chunk of h, [k_local][row]
    __shared__ float gs[64][17];    // ~4.3KB: gates transpose buffer (padded)
    __shared__ float c_s[4][64];    //  1 KB : cell state, persistent per block

    const int tid = threadIdx.x;
    const int bid = blockIdx.x;
    const int j0 = bid * 4;

    // load W_hh slice (once)
    for (int lc = 0; lc < 16; lc++) {
        int gc = (lc >> 2) * Hz + j0 + (lc & 3);
        int k = tid * 4;
        float4 v = *(const float4*)&Whh[(size_t)gc * Hz + k];
        w_s[k + 0][lc] = v.x;
        w_s[k + 1][lc] = v.y;
        w_s[k + 2][lc] = v.z;
        w_s[k + 3][lc] = v.w;
    }
    // zero cell state and my slice of h0
    for (int idx = tid; idx < 256; idx += 128) {
        c_s[idx >> 6][idx & 63] = 0.f;
        g_h0[(j0 + (idx >> 6)) * 64 + (idx & 63)] = 0.f;
    }
    __threadfence();
    gridbar();

    const int rg = tid & 15;   // row group: rows 4rg..4rg+3
    const int cp = tid >> 4;   // 0..7 -> local cols 2cp, 2cp+1
    const int row2 = tid & 63; // phase-2 row (= batch index)
    const int jh  = tid >> 6;  // 0..1 -> jj in {2jh, 2jh+1}

    const float* hprev = g_h0;
    float*       hnext = g_h1;

    for (int t = 0; t < Tz; t++) {
        // prefetch xp for phase 2 (held in regs through the GEMM)
        float2 xpv[4];
        {
            size_t base = ((size_t)row2 * Tz + t) * Gz + j0 + 2 * jh;
#pragma unroll
            for (int g = 0; g < 4; g++)
                xpv[g] = *(const float2*)&xp[base + (size_t)g * Hz];
        }

        float acc[4][2];
#pragma unroll
        for (int i = 0; i < 4; i++) { acc[i][0] = 0.f; acc[i][1] = 0.f; }

        // preload chunk 0
        float4 pre[4];
#pragma unroll
        for (int q = 0; q < 4; q++)
            pre[q] = *(const float4*)&hprev[(tid + q * 128) * 4];

        for (int kc = 0; kc < Hz; kc += 32) {
            __syncthreads();  // previous chunk consumers done
#pragma unroll
            for (int q = 0; q < 4; q++)
                ((float4*)h_s)[tid + q * 128] = pre[q];
            __syncthreads();
            if (kc + 32 < Hz) {
#pragma unroll
                for (int q = 0; q < 4; q++)
                    pre[q] = *(const float4*)&hprev[(kc + 32) * 64 + (tid + q * 128) * 4];
            }
#pragma unroll
            for (int k = 0; k < 32; k++) {
                float4 hv = *(const float4*)&h_s[k][rg * 4];
                float2 wv = *(const float2*)&w_s[kc + k][cp * 2];
                acc[0][0] += hv.x * wv.x; acc[0][1] += hv.x * wv.y;
                acc[1][0] += hv.y * wv.x; acc[1][1] += hv.y * wv.y;
                acc[2][0] += hv.z * wv.x; acc[2][1] += hv.z * wv.y;
                acc[3][0] += hv.w * wv.x; acc[3][1] += hv.w * wv.y;
            }
        }

        __syncthreads();
#pragma unroll
        for (int i = 0; i < 4; i++) {
            gs[rg * 4 + i][cp * 2 + 0] = acc[i][0];
            gs[rg * 4 + i][cp * 2 + 1] = acc[i][1];
        }
        __syncthreads();

        // phase 2: elementwise LSTM cell for (row2, jj in {2jh, 2jh+1})
#pragma unroll
        for (int s = 0; s < 2; s++) {
            int jj = 2 * jh + s;
            float xi = gs[row2][0 * 4 + jj] + (s == 0 ? xpv[0].x : xpv[0].y);
            float xf = gs[row2][1 * 4 + jj] + (s == 0 ? xpv[1].x : xpv[1].y);
            float xg = gs[row2][2 * 4 + jj] + (s == 0 ? xpv[2].x : xpv[2].y);
            float xo = gs[row2][3 * 4 + jj] + (s == 0 ? xpv[3].x : xpv[3].y);
            float iv = sigmoidf_(xi);
            float fv = sigmoidf_(xf);
            float gv = tanhf(xg);
            float ov = sigmoidf_(xo);
            float cv = fv * c_s[jj][row2] + iv * gv;
            float hv = ov * tanhf(cv);
            c_s[jj][row2] = cv;
            hnext[(j0 + jj) * 64 + row2] = hv;
            if (layer == 1) {
                g_hseq[((size_t)row2 * Tz + t) * Hz + j0 + jj] = hv;
            } else {
                outp[(size_t)row2 * (Hz * Tz) + (size_t)(j0 + jj) * Tz + t] = hv;
            }
        }

        __threadfence();
        gridbar();

        // swap h buffers
        const float* tmp = hprev;
        hprev = hnext;
        hnext = (float*)tmp;
    }
}

// ---------------- host launcher ----------------
extern "C" void kernel_launch(void* const* d_in, const int* in_sizes, int n_in,
                              void* d_out, int out_size)
{
    const float* x     = (const float*)d_in[0];
    const float* W_ih1 = (const float*)d_in[1];
    const float* W_hh1 = (const float*)d_in[2];
    const float* b_ih1 = (const float*)d_in[3];
    const float* b_hh1 = (const float*)d_in[4];
    const float* W_ih2 = (const float*)d_in[5];
    const float* W_hh2 = (const float*)d_in[6];
    const float* b_ih2 = (const float*)d_in[7];
    const float* b_hh2 = (const float*)d_in[8];
    float* out = (float*)d_out;

    // device-symbol addresses
    float *p_xp, *p_hseq, *p_wt1, *p_wt2, *p_b1, *p_b2;
    cudaGetSymbolAddress((void**)&p_xp,   g_xp);
    cudaGetSymbolAddress((void**)&p_hseq, g_hseq);
    cudaGetSymbolAddress((void**)&p_wt1,  g_wt1);
    cudaGetSymbolAddress((void**)&p_wt2,  g_wt2);
    cudaGetSymbolAddress((void**)&p_b1,   g_bias1);
    cudaGetSymbolAddress((void**)&p_b2,   g_bias2);

    // 1) prep
    lstm_prep<<<(Cz * Gz + 255) / 256, 256>>>(W_ih1, b_ih1, b_hh1, W_ih2, b_ih2, b_hh2);

    // 2) xp1 = x^T-view @ W_ih1^T + (b_ih1 + b_hh1)
    gemm_xp<true><<<dim3(Gz / 128, Mz / 128), 256>>>(x, p_wt1, p_b1, p_xp);

    // 3) recurrence layer 1 -> g_hseq
    lstm_rec<<<NBLK, 128>>>(W_hh1, p_xp, out /*unused*/, 1);

    // 4) xp2 = hseq @ W_ih2^T + (b_ih2 + b_hh2)
    gemm_xp<false><<<dim3(Gz / 128, Mz / 128), 256>>>(p_hseq, p_wt2, p_b2, p_xp);

    // 5) recurrence layer 2 -> out (B, H, T)
    lstm_rec<<<NBLK, 128>>>(W_hh2, p_xp, out, 2);
}